// round 11
// baseline (speedup 1.0000x reference)
#include <cuda_runtime.h>

#define H 1024
#define W 1024
#define NB 16
#define TILE 64
#define XOFF 8          // tile col 0 sits at buffer x=8 (so tile cols are 4-aligned)
#define YOFF 5
#define SX 80           // buffer row stride (floats)
#define NROWS 74
#define NTHREADS 256
#define NSTRIP 14       // erode y-strips (18 x-chunks * 14 strips = 252 threads)

// accumulators: [0]=A sum skel_p*t, [1]=B sum skel_p, [2]=C sum skel_t*p, [3]=D sum skel_t,
// [4+b]=inter_b, [20+b]=sum_sig_p_b, [36+b]=sum_t_b
__device__ double g_acc[52];

__device__ __forceinline__ float ex2_approx(float x) {
    float r;
    asm("ex2.approx.ftz.f32 %0, %1;" : "=f"(r) : "f"(x));
    return r;
}
__device__ __forceinline__ float rcp_approx(float x) {
    float r;
    asm("rcp.approx.ftz.f32 %0, %1;" : "=f"(r) : "f"(x));
    return r;
}
__device__ __forceinline__ float tanh_approx(float x) {
    float r;
    asm("tanh.approx.f32 %0, %1;" : "=f"(r) : "f"(x));
    return r;
}

__device__ __forceinline__ float gelu_f(float x) {
    // tanh-form gelu with HW tanh: gelu(x) = 0.5x * (1 + tanh(0.79788456*(x + 0.044715 x^3)))
    float x2 = x * x;
    float y = x * fmaf(0.0356774081f, x2, 0.7978845608f);
    float hx = 0.5f * x;
    return fmaf(hx, tanh_approx(y), hx);
}

__device__ __forceinline__ float sigmoid_f(float x) {
    float den = ex2_approx(x * -1.442695041f) + 1.0f;
    return rcp_approx(den);
}

__global__ void zero_acc_kernel() {
    int i = threadIdx.x;
    if (i < 52) g_acc[i] = 0.0;
}

__device__ __forceinline__ void load_hrow(float h[4], const float* row, bool bdry, float NINF) {
    float4 c = *(const float4*)row;
    float lf = row[-1], rg = row[4];
    if (bdry) {
        lf  = (lf  < 1e30f) ? lf  : NINF;
        c.x = (c.x < 1e30f) ? c.x : NINF;
        c.y = (c.y < 1e30f) ? c.y : NINF;
        c.z = (c.z < 1e30f) ? c.z : NINF;
        c.w = (c.w < 1e30f) ? c.w : NINF;
        rg  = (rg  < 1e30f) ? rg  : NINF;
    }
    h[0] = fmaxf(lf,  fmaxf(c.x, c.y));
    h[1] = fmaxf(c.x, fmaxf(c.y, c.z));
    h[2] = fmaxf(c.y, fmaxf(c.z, c.w));
    h[3] = fmaxf(c.z, fmaxf(c.w, rg));
}

__global__ __launch_bounds__(NTHREADS, 4)
void cldice_main(const float* __restrict__ y_pred, const float* __restrict__ y_true) {
    __shared__ float bufA[NROWS * SX];
    __shared__ float bufB[NROWS * SX];
    __shared__ float red[8][8];

    const int tid = threadIdx.x;
    const int gx0 = blockIdx.x * TILE, gy0 = blockIdx.y * TILE, b = blockIdx.z;
    const int base = b * (H * W);
    const bool bdry = (blockIdx.x == 0) | (blockIdx.x == (W/TILE - 1)) |
                      (blockIdx.y == 0) | (blockIdx.y == (H/TILE - 1));

    // 4x4 output block per thread: 16 blocks in x, 16 in y
    const int tx4 = tid & 15, ty4 = tid >> 4;
    const int sx = XOFF + tx4 * 4, sy = YOFF + ty4 * 4;

    // buffer coords valid iff gx0 + x - XOFF in [0,W) etc.
    const int xv_lo = XOFF - gx0;
    const int xv_hi = XOFF + (W - 1) - gx0;
    const int yv_lo = YOFF - gy0;
    const int yv_hi = YOFF + (H - 1) - gy0;

    // erode strip mapping: 18 x-chunks * 14 y-strips
    const int ys = tid / 18;              // 0..14 (>=14 -> idle)
    const int xc = tid - ys * 18;
    const int ex4 = 4 + xc * 4;           // x in [4,75]

    // vector-load mapping: 20 float4-chunks per 80-wide row (256 = 12*20 + 16)
    const int vy0 = tid / 20;
    const int vx0 = tid - vy0 * 20;

    float skel[16];
    float accA = 0.f, accB = 0.f, accC = 0.f, accD = 0.f;
    float accI = 0.f, accP = 0.f, accT = 0.f;

    const float INF = __int_as_float(0x7f800000);
    const float NINF = __int_as_float(0xff800000);

    #pragma unroll 1
    for (int t = 0; t < 2; ++t) {
        const float* src = t ? y_true : y_pred;
        float* b0 = bufA;
        float* b1 = bufB;

        // ---- load halo tile ----
        if (!bdry) {
            // interior: full 80-wide rows, float4, no bounds checks
            const float* gsrc = src + base + (gy0 - YOFF) * W + gx0 - XOFF;
            int y = vy0, x = vx0;
            while (y < NROWS) {
                *(float4*)(b0 + y * SX + x * 4) = *(const float4*)(gsrc + y * W + x * 4);
                x += 16; y += 12;
                if (x >= 20) { x -= 20; y += 1; }
            }
        } else {
            // boundary: scalar predicated path, x in [3,76], y in [0,73]; OOB -> +INF
            for (int i = tid; i < 74 * 74; i += NTHREADS) {
                int yy = i / 74, xx = i - yy * 74;
                int x = xx + 3;
                int gy = gy0 + yy - YOFF, gx = gx0 + x - XOFF;
                bool ok = (gy >= 0) & (gy < H) & (gx >= 0) & (gx < W);
                b0[yy * SX + x] = ok ? __ldg(src + base + gy * W + gx) : INF;
            }
        }
        __syncthreads();

        #pragma unroll 1
        for (int lvl = 0; lvl < 4; ++lvl) {
            // ---- erode (plus-min): strip-based rolling 3-row window, b0 -> b1 ----
            const int yl = 1 + lvl;
            const int ny = 72 - 2 * lvl;
            int rows = 0, y0 = 0;
            if (ys < NSTRIP) {
                int bse = ny / NSTRIP, rem = ny - bse * NSTRIP;
                rows = bse + (ys < rem ? 1 : 0);
                y0 = yl + ys * bse + (ys < rem ? ys : rem);
            }
            if (rows > 0) {
                const float* pbase = b0 + y0 * SX + ex4;
                float4 uc = *(const float4*)(pbase - SX);   // row y0-1 center
                float4 pc = *(const float4*)pbase;          // row y0 center
                float pl = pbase[-1], pr = pbase[4];
                #pragma unroll 1
                for (int r = 0; r < rows; ++r) {
                    const float* nrow = b0 + (y0 + r + 1) * SX + ex4;
                    float4 nc = *(const float4*)nrow;
                    float nl = nrow[-1], nr2 = nrow[4];
                    float4 o;
                    o.x = fminf(fminf(pc.x, fminf(pl,   pc.y)), fminf(uc.x, nc.x));
                    o.y = fminf(fminf(pc.y, fminf(pc.x, pc.z)), fminf(uc.y, nc.y));
                    o.z = fminf(fminf(pc.z, fminf(pc.y, pc.w)), fminf(uc.z, nc.z));
                    o.w = fminf(fminf(pc.w, fminf(pc.z, pr  )), fminf(uc.w, nc.w));
                    int y = y0 + r;
                    if (bdry) {
                        bool yok = (y >= yv_lo) & (y <= yv_hi);
                        o.x = (yok & (ex4 + 0 >= xv_lo) & (ex4 + 0 <= xv_hi)) ? o.x : INF;
                        o.y = (yok & (ex4 + 1 >= xv_lo) & (ex4 + 1 <= xv_hi)) ? o.y : INF;
                        o.z = (yok & (ex4 + 2 >= xv_lo) & (ex4 + 2 <= xv_hi)) ? o.z : INF;
                        o.w = (yok & (ex4 + 3 >= xv_lo) & (ex4 + 3 <= xv_hi)) ? o.w : INF;
                    }
                    *(float4*)(b1 + y * SX + ex4) = o;
                    uc = pc; pc = nc; pl = nl; pr = nr2;
                }
            }

            // ---- cache own 4x4 a-values from b0 BEFORE the sync ----
            // (all b0 reads complete pre-sync; post-sync, next level's erode may
            //  safely overwrite b0 while this level's dilate reads only b1 + regs)
            float4 ac[4];
            #pragma unroll
            for (int r = 0; r < 4; ++r)
                ac[r] = *(const float4*)(b0 + (sy + r) * SX + sx);

            __syncthreads();

            // ---- dilate 3x3 (rolling 3-row window) + delta + skel update ----
            float h0[4], h1[4], h2[4];
            load_hrow(h0, b1 + (sy - 1) * SX + sx, bdry, NINF);
            load_hrow(h1, b1 + sy * SX + sx, bdry, NINF);
            #pragma unroll
            for (int r = 0; r < 4; ++r) {
                load_hrow(h2, b1 + (sy + 1 + r) * SX + sx, bdry, NINF);
                float av[4] = {ac[r].x, ac[r].y, ac[r].z, ac[r].w};
                #pragma unroll
                for (int c = 0; c < 4; ++c) {
                    float m = fmaxf(h0[c], fmaxf(h1[c], h2[c]));
                    float delta = gelu_f(av[c] - m);
                    int j = r * 4 + c;
                    if (lvl == 0) skel[j] = delta;
                    else          skel[j] += gelu_f(delta - skel[j] * delta);
                }
                #pragma unroll
                for (int c = 0; c < 4; ++c) { h0[c] = h1[c]; h1[c] = h2[c]; }
            }
            // no sync here: next erode writes old-b0, whose readers all finished pre-sync
            float* tmp = b0; b0 = b1; b1 = tmp;
        }
        // protect bufA/bufB before next image's load overwrites them
        __syncthreads();

        // ---- epilogue: accumulate skel sums + dice terms from gmem (L2-hot) ----
        #pragma unroll
        for (int r = 0; r < 4; ++r) {
            const int goff = base + (gy0 + sy - YOFF + r) * W + gx0 + sx - XOFF;
            if (t == 0) {
                const float4 t4 = *(const float4*)(y_true + goff);
                const float4 q4 = *(const float4*)(y_pred + goff);
                float tvv[4] = {t4.x, t4.y, t4.z, t4.w};
                float qvv[4] = {q4.x, q4.y, q4.z, q4.w};
                #pragma unroll
                for (int c = 0; c < 4; ++c) {
                    int j = r * 4 + c;
                    accA += skel[j] * tvv[c];
                    accB += skel[j];
                    float s = sigmoid_f(qvv[c]);
                    accI += s * tvv[c];
                    accP += s;
                    accT += tvv[c];
                }
            } else {
                const float4 p4 = *(const float4*)(y_pred + goff);
                float pvv[4] = {p4.x, p4.y, p4.z, p4.w};
                #pragma unroll
                for (int c = 0; c < 4; ++c) {
                    int j = r * 4 + c;
                    accC += skel[j] * pvv[c];
                    accD += skel[j];
                }
            }
        }
    }

    // ---- block reduction of 7 partials, then one double atomic each ----
    float vals[7] = {accA, accB, accC, accD, accI, accP, accT};
    int lane = tid & 31, warp = tid >> 5;
    #pragma unroll
    for (int k = 0; k < 7; ++k) {
        float v = vals[k];
        #pragma unroll
        for (int o = 16; o > 0; o >>= 1) v += __shfl_down_sync(0xffffffffu, v, o);
        if (lane == 0) red[warp][k] = v;
    }
    __syncthreads();
    if (warp == 0 && lane < 7) {
        float s = 0.f;
        #pragma unroll
        for (int w = 0; w < 8; ++w) s += red[w][lane];
        int idx = (lane < 4) ? lane : (4 + (lane - 4) * 16 + b);
        atomicAdd(&g_acc[idx], (double)s);
    }
}

__global__ void finalize_kernel(float* out, int n) {
    if (threadIdx.x == 0) {
        double A = g_acc[0], B = g_acc[1], C = g_acc[2], D = g_acc[3];
        double tprec = (A + 1.0) / (B + 1.0);
        double tsens = (C + 1.0) / (D + 1.0);
        double cl = 1.0 - 2.0 * (tprec * tsens) / (tprec + tsens);
        double dsum = 0.0;
        for (int i = 0; i < 16; ++i) {
            double gd = (2.0 * g_acc[4 + i] + 1e-4) / (g_acc[20 + i] + g_acc[36 + i] + 1e-4);
            dsum += 1.0 - gd;
        }
        double dice = dsum / 16.0;
        double res = 0.5 * cl + 0.5 * dice;
        for (int i = 0; i < n; ++i) out[i] = (float)res;
    }
}

extern "C" void kernel_launch(void* const* d_in, const int* in_sizes, int n_in,
                              void* d_out, int out_size) {
    const float* y_pred = (const float*)d_in[0];
    const float* y_true = (const float*)d_in[1];
    (void)in_sizes; (void)n_in;

    zero_acc_kernel<<<1, 64>>>();
    dim3 grid(W / TILE, H / TILE, NB);
    cldice_main<<<grid, NTHREADS>>>(y_pred, y_true);
    finalize_kernel<<<1, 32>>>((float*)d_out, out_size);
}

// round 12
// speedup vs baseline: 1.6186x; 1.6186x over previous
#include <cuda_runtime.h>

#define H 1024
#define W 1024
#define NB 16
#define TILE 64
#define XOFF 8          // tile col 0 sits at buffer x=8 (so tile cols are 4-aligned)
#define YOFF 5
#define SX 80           // buffer row stride (floats)
#define NROWS 74
#define NTHREADS 256
#define NSTRIP 14       // erode y-strips (18 x-chunks * 14 strips = 252 threads)

// accumulators: [0]=A sum skel_p*t, [1]=B sum skel_p, [2]=C sum skel_t*p, [3]=D sum skel_t,
// [4+b]=inter_b, [20+b]=sum_sig_p_b, [36+b]=sum_t_b
__device__ double g_acc[52];

__device__ __forceinline__ float ex2_approx(float x) {
    float r;
    asm("ex2.approx.ftz.f32 %0, %1;" : "=f"(r) : "f"(x));
    return r;
}
__device__ __forceinline__ float rcp_approx(float x) {
    float r;
    asm("rcp.approx.ftz.f32 %0, %1;" : "=f"(r) : "f"(x));
    return r;
}
__device__ __forceinline__ float tanh_approx(float x) {
    float r;
    asm("tanh.approx.f32 %0, %1;" : "=f"(r) : "f"(x));
    return r;
}

__device__ __forceinline__ float gelu_f(float x) {
    // tanh-form gelu with HW tanh: gelu(x) = 0.5x * (1 + tanh(0.79788456*(x + 0.044715 x^3)))
    float x2 = x * x;
    float y = x * fmaf(0.0356774081f, x2, 0.7978845608f);
    float hx = 0.5f * x;
    return fmaf(hx, tanh_approx(y), hx);
}

__device__ __forceinline__ float sigmoid_f(float x) {
    float den = ex2_approx(x * -1.442695041f) + 1.0f;
    return rcp_approx(den);
}

__global__ void zero_acc_kernel() {
    int i = threadIdx.x;
    if (i < 52) g_acc[i] = 0.0;
}

__device__ __forceinline__ void load_hrow(float h[4], const float* row, bool bdry, float NINF) {
    float4 c = *(const float4*)row;
    float lf = row[-1], rg = row[4];
    if (bdry) {
        lf  = (lf  < 1e30f) ? lf  : NINF;
        c.x = (c.x < 1e30f) ? c.x : NINF;
        c.y = (c.y < 1e30f) ? c.y : NINF;
        c.z = (c.z < 1e30f) ? c.z : NINF;
        c.w = (c.w < 1e30f) ? c.w : NINF;
        rg  = (rg  < 1e30f) ? rg  : NINF;
    }
    h[0] = fmaxf(lf,  fmaxf(c.x, c.y));
    h[1] = fmaxf(c.x, fmaxf(c.y, c.z));
    h[2] = fmaxf(c.y, fmaxf(c.z, c.w));
    h[3] = fmaxf(c.z, fmaxf(c.w, rg));
}

__global__ __launch_bounds__(NTHREADS, 4)
void cldice_main(const float* __restrict__ y_pred, const float* __restrict__ y_true) {
    __shared__ float bufA[NROWS * SX];
    __shared__ float bufB[NROWS * SX];
    __shared__ float red[8][8];

    const int tid = threadIdx.x;
    const int gx0 = blockIdx.x * TILE, gy0 = blockIdx.y * TILE, b = blockIdx.z;
    const int base = b * (H * W);
    const bool bdry = (blockIdx.x == 0) | (blockIdx.x == (W/TILE - 1)) |
                      (blockIdx.y == 0) | (blockIdx.y == (H/TILE - 1));

    // 4x4 output block per thread: 16 blocks in x, 16 in y
    const int tx4 = tid & 15, ty4 = tid >> 4;
    const int sx = XOFF + tx4 * 4, sy = YOFF + ty4 * 4;

    // buffer coords valid iff gx0 + x - XOFF in [0,W) etc.
    const int xv_lo = XOFF - gx0;
    const int xv_hi = XOFF + (W - 1) - gx0;
    const int yv_lo = YOFF - gy0;
    const int yv_hi = YOFF + (H - 1) - gy0;

    // erode strip mapping: 18 x-chunks * 14 y-strips
    const int ys = tid / 18;              // 0..14 (>=14 -> idle)
    const int xc = tid - ys * 18;
    const int ex4 = 4 + xc * 4;           // x in [4,75]

    // vector-load mapping: 20 float4-chunks per 80-wide row
    const int vy0 = tid / 20;
    const int vx0 = tid - vy0 * 20;

    float skel[16];
    float accA = 0.f, accB = 0.f, accC = 0.f, accD = 0.f;
    float accI = 0.f, accP = 0.f, accT = 0.f;

    const float INF = __int_as_float(0x7f800000);
    const float NINF = __int_as_float(0xff800000);

    #pragma unroll 1
    for (int t = 0; t < 2; ++t) {
        const float* src = t ? y_true : y_pred;
        float* b0 = bufA;
        float* b1 = bufB;

        // ---- load halo tile ----
        if (!bdry) {
            // interior: full 80-wide rows, float4, no bounds checks
            const float* gsrc = src + base + (gy0 - YOFF) * W + gx0 - XOFF;
            int y = vy0, x = vx0;
            while (y < NROWS) {
                *(float4*)(b0 + y * SX + x * 4) = *(const float4*)(gsrc + y * W + x * 4);
                x += 16; y += 12;
                if (x >= 20) { x -= 20; y += 1; }
            }
        } else {
            // boundary: scalar predicated path, x in [3,76], y in [0,73]; OOB -> +INF
            for (int i = tid; i < 74 * 74; i += NTHREADS) {
                int yy = i / 74, xx = i - yy * 74;
                int x = xx + 3;
                int gy = gy0 + yy - YOFF, gx = gx0 + x - XOFF;
                bool ok = (gy >= 0) & (gy < H) & (gx >= 0) & (gx < W);
                b0[yy * SX + x] = ok ? __ldg(src + base + gy * W + gx) : INF;
            }
        }
        __syncthreads();

        #pragma unroll 1
        for (int lvl = 0; lvl < 4; ++lvl) {
            // ---- erode (plus-min): strip-based rolling 3-row window ----
            const int yl = 1 + lvl;
            const int ny = 72 - 2 * lvl;
            int rows = 0, y0 = 0;
            if (ys < NSTRIP) {
                int bse = ny / NSTRIP, rem = ny - bse * NSTRIP;
                rows = bse + (ys < rem ? 1 : 0);
                y0 = yl + ys * bse + (ys < rem ? ys : rem);
            }
            if (rows > 0) {
                const float* pbase = b0 + y0 * SX + ex4;
                float4 uc = *(const float4*)(pbase - SX);   // row y0-1 center
                float4 pc = *(const float4*)pbase;          // row y0 center
                float pl = pbase[-1], pr = pbase[4];
                #pragma unroll 1
                for (int r = 0; r < rows; ++r) {
                    const float* nrow = b0 + (y0 + r + 1) * SX + ex4;
                    float4 nc = *(const float4*)nrow;
                    float nl = nrow[-1], nr2 = nrow[4];
                    float4 o;
                    o.x = fminf(fminf(pc.x, fminf(pl,   pc.y)), fminf(uc.x, nc.x));
                    o.y = fminf(fminf(pc.y, fminf(pc.x, pc.z)), fminf(uc.y, nc.y));
                    o.z = fminf(fminf(pc.z, fminf(pc.y, pc.w)), fminf(uc.z, nc.z));
                    o.w = fminf(fminf(pc.w, fminf(pc.z, pr  )), fminf(uc.w, nc.w));
                    int y = y0 + r;
                    if (bdry) {
                        bool yok = (y >= yv_lo) & (y <= yv_hi);
                        o.x = (yok & (ex4 + 0 >= xv_lo) & (ex4 + 0 <= xv_hi)) ? o.x : INF;
                        o.y = (yok & (ex4 + 1 >= xv_lo) & (ex4 + 1 <= xv_hi)) ? o.y : INF;
                        o.z = (yok & (ex4 + 2 >= xv_lo) & (ex4 + 2 <= xv_hi)) ? o.z : INF;
                        o.w = (yok & (ex4 + 3 >= xv_lo) & (ex4 + 3 <= xv_hi)) ? o.w : INF;
                    }
                    *(float4*)(b1 + y * SX + ex4) = o;
                    uc = pc; pc = nc; pl = nl; pr = nr2;
                }
            }
            __syncthreads();

            // ---- dilate 3x3 (rolling 3-row window) + delta + skel update ----
            float h0[4], h1[4], h2[4];
            load_hrow(h0, b1 + (sy - 1) * SX + sx, bdry, NINF);
            load_hrow(h1, b1 + sy * SX + sx, bdry, NINF);
            #pragma unroll
            for (int r = 0; r < 4; ++r) {
                load_hrow(h2, b1 + (sy + 1 + r) * SX + sx, bdry, NINF);
                const float4 a4 = *(const float4*)(b0 + (sy + r) * SX + sx);
                float av[4] = {a4.x, a4.y, a4.z, a4.w};
                #pragma unroll
                for (int c = 0; c < 4; ++c) {
                    float m = fmaxf(h0[c], fmaxf(h1[c], h2[c]));
                    float delta = gelu_f(av[c] - m);
                    int j = r * 4 + c;
                    if (lvl == 0) skel[j] = delta;
                    else          skel[j] += gelu_f(delta - skel[j] * delta);
                }
                #pragma unroll
                for (int c = 0; c < 4; ++c) { h0[c] = h1[c]; h1[c] = h2[c]; }
            }
            __syncthreads();
            float* tmp = b0; b0 = b1; b1 = tmp;
        }

        // ---- epilogue: accumulate skel sums + dice terms from gmem (L2-hot) ----
        #pragma unroll
        for (int r = 0; r < 4; ++r) {
            const int goff = base + (gy0 + sy - YOFF + r) * W + gx0 + sx - XOFF;
            if (t == 0) {
                const float4 t4 = *(const float4*)(y_true + goff);
                const float4 q4 = *(const float4*)(y_pred + goff);
                float tvv[4] = {t4.x, t4.y, t4.z, t4.w};
                float qvv[4] = {q4.x, q4.y, q4.z, q4.w};
                #pragma unroll
                for (int c = 0; c < 4; ++c) {
                    int j = r * 4 + c;
                    accA += skel[j] * tvv[c];
                    accB += skel[j];
                    float s = sigmoid_f(qvv[c]);
                    accI += s * tvv[c];
                    accP += s;
                    accT += tvv[c];
                }
            } else {
                const float4 p4 = *(const float4*)(y_pred + goff);
                float pvv[4] = {p4.x, p4.y, p4.z, p4.w};
                #pragma unroll
                for (int c = 0; c < 4; ++c) {
                    int j = r * 4 + c;
                    accC += skel[j] * pvv[c];
                    accD += skel[j];
                }
            }
        }
    }

    // ---- block reduction of 7 partials, then one double atomic each ----
    float vals[7] = {accA, accB, accC, accD, accI, accP, accT};
    int lane = tid & 31, warp = tid >> 5;
    #pragma unroll
    for (int k = 0; k < 7; ++k) {
        float v = vals[k];
        #pragma unroll
        for (int o = 16; o > 0; o >>= 1) v += __shfl_down_sync(0xffffffffu, v, o);
        if (lane == 0) red[warp][k] = v;
    }
    __syncthreads();
    if (warp == 0 && lane < 7) {
        float s = 0.f;
        #pragma unroll
        for (int w = 0; w < 8; ++w) s += red[w][lane];
        int idx = (lane < 4) ? lane : (4 + (lane - 4) * 16 + b);
        atomicAdd(&g_acc[idx], (double)s);
    }
}

__global__ void finalize_kernel(float* out, int n) {
    if (threadIdx.x == 0) {
        double A = g_acc[0], B = g_acc[1], C = g_acc[2], D = g_acc[3];
        double tprec = (A + 1.0) / (B + 1.0);
        double tsens = (C + 1.0) / (D + 1.0);
        double cl = 1.0 - 2.0 * (tprec * tsens) / (tprec + tsens);
        double dsum = 0.0;
        for (int i = 0; i < 16; ++i) {
            double gd = (2.0 * g_acc[4 + i] + 1e-4) / (g_acc[20 + i] + g_acc[36 + i] + 1e-4);
            dsum += 1.0 - gd;
        }
        double dice = dsum / 16.0;
        double res = 0.5 * cl + 0.5 * dice;
        for (int i = 0; i < n; ++i) out[i] = (float)res;
    }
}

extern "C" void kernel_launch(void* const* d_in, const int* in_sizes, int n_in,
                              void* d_out, int out_size) {
    const float* y_pred = (const float*)d_in[0];
    const float* y_true = (const float*)d_in[1];
    (void)in_sizes; (void)n_in;

    zero_acc_kernel<<<1, 64>>>();
    dim3 grid(W / TILE, H / TILE, NB);
    cldice_main<<<grid, NTHREADS>>>(y_pred, y_true);
    finalize_kernel<<<1, 32>>>((float*)d_out, out_size);
}